// round 7
// baseline (speedup 1.0000x reference)
#include <cuda_runtime.h>
#include <cuda_bf16.h>
#include <mma.h>

using namespace nvcuda;

// Problem constants
#define BB 4
#define SS 1024
#define DD 4096
#define HH 32
#define HD 128
#define BS (BB*SS)        // 4096 rows
#define NEG_INF (-1e30f)

// ---------------------------------------------------------------------------
// Scratch (allocation-free rule: __device__ globals)
// ---------------------------------------------------------------------------
__device__ float g_q[BS * DD];
__device__ float g_k[BS * DD];
__device__ float g_v[BS * DD];
__device__ float g_attn[BS * DD];

// ---------------------------------------------------------------------------
// cp.async helpers
// ---------------------------------------------------------------------------
__device__ __forceinline__ void cp_async16(void* smem_dst, const void* gsrc) {
    unsigned sa = (unsigned)__cvta_generic_to_shared(smem_dst);
    asm volatile("cp.async.cg.shared.global [%0], [%1], 16;\n" :: "r"(sa), "l"(gsrc));
}
__device__ __forceinline__ void cp_async_commit() {
    asm volatile("cp.async.commit_group;\n");
}
template<int N>
__device__ __forceinline__ void cp_async_wait() {
    asm volatile("cp.async.wait_group %0;\n" :: "n"(N));
}

// ---------------------------------------------------------------------------
// TF32 tensor-core GEMM:  C[M,N] = A[M,K] * W[N,K]^T   (M=N=K=4096)
// 3xTF32 error compensation: A = Ah + Al, B = Bh + Bl (tf32 splits),
//   C ~= Ah*Bh + Ah*Bl + Al*Bh   (drops only the ~2^-22 Al*Bl term)
// CTA tile 128x128, BK=16, 256 threads (8 warps as 2x4, warp tile 64x32).
// cp.async double-buffered. Optional fused RoPE epilogue via smem staging.
// ---------------------------------------------------------------------------
#define BK 16
#define BKP 20                    // padded k-stride (floats), 80B = 16B-aligned
#define AB_BUF (128 * BKP)        // 2560 floats per matrix per stage
#define STG_STRIDE 132

template<bool ROPE>
__global__ __launch_bounds__(256)
void gemm_tc_kernel(const float* __restrict__ A,
                    const float* __restrict__ W,
                    float* __restrict__ C,
                    const float* __restrict__ cosb,
                    const float* __restrict__ sinb)
{
    extern __shared__ float sm[];
    // pipeline buffers: [A0][B0][A1][B1], each AB_BUF floats
    // staging (epilogue only, reuses same memory): 128 x STG_STRIDE floats

    const int tid = threadIdx.x;
    const int wid = tid >> 5;
    const int wm  = wid >> 2;            // 0..1  -> m offset wm*64
    const int wn  = wid & 3;             // 0..3  -> n offset wn*32
    const int m0  = blockIdx.y * 128;
    const int n0  = blockIdx.x * 128;

    // global load mapping: 128 rows x 16 cols per matrix per stage,
    // each thread: 2 float4 per matrix (rows r, r+64)
    const int lr = tid >> 2;             // 0..63
    const int lc = (tid & 3) << 2;       // 0,4,8,12

    wmma::fragment<wmma::accumulator, 16, 16, 8, float> acc[4][2];
    #pragma unroll
    for (int i = 0; i < 4; i++)
        #pragma unroll
        for (int j = 0; j < 2; j++)
            wmma::fill_fragment(acc[i][j], 0.f);

    const int nt = DD / BK;              // 256 k-tiles

    // ---- stage issuer
    auto issue = [&](int t) {
        const int buf = t & 1;
        const int k0 = t * BK;
        float* sA = sm + buf * 2 * AB_BUF;
        float* sB = sA + AB_BUF;
        #pragma unroll
        for (int i = 0; i < 2; i++) {
            const int r = lr + i * 64;
            cp_async16(sA + r * BKP + lc, A + (size_t)(m0 + r) * DD + k0 + lc);
            cp_async16(sB + r * BKP + lc, W + (size_t)(n0 + r) * DD + k0 + lc);
        }
    };

    issue(0);
    cp_async_commit();

    for (int t = 0; t < nt; t++) {
        if (t + 1 < nt) {
            issue(t + 1);
            cp_async_commit();
            cp_async_wait<1>();
        } else {
            cp_async_wait<0>();
        }
        __syncthreads();

        const int buf = t & 1;
        const float* sA = sm + buf * 2 * AB_BUF;
        const float* sB = sA + AB_BUF;

        #pragma unroll
        for (int ks = 0; ks < BK; ks += 8) {
            // A fragments (hi/lo) for this warp's 4 m-subtiles
            wmma::fragment<wmma::matrix_a, 16, 16, 8, wmma::precision::tf32, wmma::row_major> ah[4], al[4];
            #pragma unroll
            for (int mm = 0; mm < 4; mm++) {
                wmma::fragment<wmma::matrix_a, 16, 16, 8, wmma::precision::tf32, wmma::row_major> tmp;
                wmma::load_matrix_sync(tmp, sA + (wm * 64 + mm * 16) * BKP + ks, BKP);
                #pragma unroll
                for (int e = 0; e < tmp.num_elements; e++) {
                    float v = tmp.x[e];
                    float h = wmma::__float_to_tf32(v);
                    ah[mm].x[e] = h;
                    al[mm].x[e] = wmma::__float_to_tf32(v - h);
                }
            }
            #pragma unroll
            for (int nn = 0; nn < 2; nn++) {
                wmma::fragment<wmma::matrix_b, 16, 16, 8, wmma::precision::tf32, wmma::col_major> tb, bh, bl;
                wmma::load_matrix_sync(tb, sB + (wn * 32 + nn * 16) * BKP + ks, BKP);
                #pragma unroll
                for (int e = 0; e < tb.num_elements; e++) {
                    float v = tb.x[e];
                    float h = wmma::__float_to_tf32(v);
                    bh.x[e] = h;
                    bl.x[e] = wmma::__float_to_tf32(v - h);
                }
                #pragma unroll
                for (int mm = 0; mm < 4; mm++) {
                    wmma::mma_sync(acc[mm][nn], ah[mm], bh, acc[mm][nn]);
                    wmma::mma_sync(acc[mm][nn], ah[mm], bl, acc[mm][nn]);
                    wmma::mma_sync(acc[mm][nn], al[mm], bh, acc[mm][nn]);
                }
            }
        }
        __syncthreads();
    }

    // ---- epilogue via smem staging (fragment layout stays opaque)
    float* stg = sm;
    #pragma unroll
    for (int mm = 0; mm < 4; mm++)
        #pragma unroll
        for (int nn = 0; nn < 2; nn++)
            wmma::store_matrix_sync(stg + (wm * 64 + mm * 16) * STG_STRIDE + wn * 32 + nn * 16,
                                    acc[mm][nn], STG_STRIDE, wmma::mem_row_major);
    __syncthreads();

    const int er = tid >> 1;             // 0..127 (row within tile)
    const int ec = (tid & 1) * 64;       // column half
    const int gm = m0 + er;
    const int sp = gm & (SS - 1);
    #pragma unroll
    for (int j = 0; j < 64; j += 4) {
        float4 v = *(const float4*)(stg + er * STG_STRIDE + ec + j);
        if (ROPE) {
            const int col = ec + j;      // head-local (n0 mult of 128 == HD)
            const int pi = col >> 1;
            const float c0 = cosb[sp * (HD / 2) + pi];
            const float s0 = sinb[sp * (HD / 2) + pi];
            const float c1 = cosb[sp * (HD / 2) + pi + 1];
            const float s1 = sinb[sp * (HD / 2) + pi + 1];
            float re = v.x, im = v.y;
            v.x = re * c0 - im * s0;
            v.y = re * s0 + im * c0;
            re = v.z; im = v.w;
            v.z = re * c1 - im * s1;
            v.w = re * s1 + im * c1;
        }
        *(float4*)(C + (size_t)gm * DD + n0 + ec + j) = v;
    }
}

#define GEMM_SMEM_BYTES (128 * STG_STRIDE * 4)   // 67584 B (> 4*AB_BUF*4 = 40960)

// ---------------------------------------------------------------------------
// Flash attention (causal), fp32.
// grid = (S/64, B*H). CTA: 64 q-rows, loop over 64-row KV tiles (0..qb).
// ---------------------------------------------------------------------------
#define QT_STRIDE 65
#define V_STRIDE 132
#define SC_STRIDE 65

__global__ __launch_bounds__(256)
void attn_kernel(const float* __restrict__ Q,
                 const float* __restrict__ K,
                 const float* __restrict__ V,
                 float* __restrict__ O)
{
    extern __shared__ float sma[];
    float* qT   = sma;                        // [128][65]  (transposed)
    float* kT   = qT + 128 * QT_STRIDE;       // [128][65]  (transposed)
    float* vs   = kT + 128 * QT_STRIDE;       // [64][132]
    float* sc   = vs + 64 * V_STRIDE;         // [64][65]   scores/probs
    float* m_s  = sc + 64 * SC_STRIDE;        // [64]
    float* l_s  = m_s + 64;                   // [64]
    float* al_s = l_s + 64;                   // [64]

    const int tid = threadIdx.x;
    const int qb  = blockIdx.x;
    const int bh  = blockIdx.y;
    const int b   = bh >> 5;
    const int h   = bh & 31;
    const size_t headoff = (size_t)h * HD;
    const int q0 = qb * 64;

    for (int t = tid; t < 64 * 128; t += 256) {
        const int r = t >> 7, d = t & 127;
        qT[d * QT_STRIDE + r] =
            Q[(size_t)(b * SS + q0 + r) * DD + headoff + d];
    }
    if (tid < 64) { m_s[tid] = NEG_INF; l_s[tid] = 0.f; }

    const int tx = tid & 15, ty = tid >> 4;
    const int r0  = ty * 4;
    const int c0s = tx * 4;

    float o[4][8];
    #pragma unroll
    for (int i = 0; i < 4; i++)
        #pragma unroll
        for (int cc = 0; cc < 8; cc++) o[i][cc] = 0.f;

    const float scale = 0.088388347648318447f;  // 1/sqrt(128)

    for (int kv = 0; kv <= qb; kv++) {
        const int k0r = kv * 64;
        __syncthreads();

        for (int t = tid; t < 64 * 128; t += 256) {
            const int r = t >> 7, d = t & 127;
            const size_t g = (size_t)(b * SS + k0r + r) * DD + headoff + d;
            kT[d * QT_STRIDE + r] = K[g];
            vs[r * V_STRIDE + d]  = V[g];
        }
        __syncthreads();

        float s4[4][4];
        #pragma unroll
        for (int i = 0; i < 4; i++)
            #pragma unroll
            for (int j = 0; j < 4; j++) s4[i][j] = 0.f;

        #pragma unroll 4
        for (int kk = 0; kk < 128; kk++) {
            float a[4], bb2[4];
            #pragma unroll
            for (int i = 0; i < 4; i++) a[i]   = qT[kk * QT_STRIDE + r0 + i];
            #pragma unroll
            for (int j = 0; j < 4; j++) bb2[j] = kT[kk * QT_STRIDE + c0s + j];
            #pragma unroll
            for (int i = 0; i < 4; i++)
                #pragma unroll
                for (int j = 0; j < 4; j++)
                    s4[i][j] += a[i] * bb2[j];
        }
        #pragma unroll
        for (int i = 0; i < 4; i++)
            #pragma unroll
            for (int j = 0; j < 4; j++)
                sc[(r0 + i) * SC_STRIDE + c0s + j] = s4[i][j];
        __syncthreads();

        {
            const int wp = tid >> 5, ln = tid & 31;
            const bool diag = (kv == qb);
            for (int rr = 0; rr < 8; rr++) {
                const int r = wp * 8 + rr;
                const int qidx = q0 + r;
                float v0 = sc[r * SC_STRIDE + ln] * scale;
                float v1 = sc[r * SC_STRIDE + 32 + ln] * scale;
                if (diag) {
                    if (k0r + ln > qidx)      v0 = NEG_INF;
                    if (k0r + 32 + ln > qidx) v1 = NEG_INF;
                }
                float mx = fmaxf(v0, v1);
                #pragma unroll
                for (int off = 16; off; off >>= 1)
                    mx = fmaxf(mx, __shfl_xor_sync(0xffffffffu, mx, off));
                const float mold = m_s[r];
                const float mnew = fmaxf(mold, mx);
                const float p0 = __expf(v0 - mnew);
                const float p1 = __expf(v1 - mnew);
                float sum = p0 + p1;
                #pragma unroll
                for (int off = 16; off; off >>= 1)
                    sum += __shfl_xor_sync(0xffffffffu, sum, off);
                sc[r * SC_STRIDE + ln]      = p0;
                sc[r * SC_STRIDE + 32 + ln] = p1;
                if (ln == 0) {
                    const float alpha = __expf(mold - mnew);
                    al_s[r] = alpha;
                    m_s[r]  = mnew;
                    l_s[r]  = l_s[r] * alpha + sum;
                }
            }
        }
        __syncthreads();

        float a4[4];
        #pragma unroll
        for (int i = 0; i < 4; i++) a4[i] = al_s[r0 + i];
        #pragma unroll
        for (int i = 0; i < 4; i++)
            #pragma unroll
            for (int cc = 0; cc < 8; cc++) o[i][cc] *= a4[i];

        #pragma unroll 2
        for (int j = 0; j < 64; j++) {
            float p[4], vv[8];
            #pragma unroll
            for (int i = 0; i < 4; i++) p[i] = sc[(r0 + i) * SC_STRIDE + j];
            #pragma unroll
            for (int cc = 0; cc < 8; cc++) vv[cc] = vs[j * V_STRIDE + tx + 16 * cc];
            #pragma unroll
            for (int i = 0; i < 4; i++)
                #pragma unroll
                for (int cc = 0; cc < 8; cc++)
                    o[i][cc] += p[i] * vv[cc];
        }
    }

    #pragma unroll
    for (int i = 0; i < 4; i++) {
        const float inv = 1.f / l_s[r0 + i];
        const size_t base = (size_t)(b * SS + q0 + r0 + i) * DD + headoff;
        #pragma unroll
        for (int cc = 0; cc < 8; cc++)
            O[base + tx + 16 * cc] = o[i][cc] * inv;
    }
}

// ---------------------------------------------------------------------------
// kernel_launch
// inputs: 0:x 1:wq 2:wk 3:wv 4:wo 5:freqs_cos 6:freqs_sin 7:mask(unused)
// ---------------------------------------------------------------------------
extern "C" void kernel_launch(void* const* d_in, const int* in_sizes, int n_in,
                              void* d_out, int out_size)
{
    const float* x    = (const float*)d_in[0];
    const float* wq   = (const float*)d_in[1];
    const float* wk   = (const float*)d_in[2];
    const float* wv   = (const float*)d_in[3];
    const float* wo   = (const float*)d_in[4];
    const float* cosb = (const float*)d_in[5];
    const float* sinb = (const float*)d_in[6];
    float* out = (float*)d_out;

    float *pq, *pk, *pv, *pa;
    cudaGetSymbolAddress((void**)&pq, g_q);
    cudaGetSymbolAddress((void**)&pk, g_k);
    cudaGetSymbolAddress((void**)&pv, g_v);
    cudaGetSymbolAddress((void**)&pa, g_attn);

    cudaFuncSetAttribute(gemm_tc_kernel<true>,
                         cudaFuncAttributeMaxDynamicSharedMemorySize, GEMM_SMEM_BYTES);
    cudaFuncSetAttribute(gemm_tc_kernel<false>,
                         cudaFuncAttributeMaxDynamicSharedMemorySize, GEMM_SMEM_BYTES);

    const int attn_smem = (128 * QT_STRIDE * 2 + 64 * V_STRIDE +
                           64 * SC_STRIDE + 3 * 64) * (int)sizeof(float);
    cudaFuncSetAttribute(attn_kernel,
                         cudaFuncAttributeMaxDynamicSharedMemorySize, attn_smem);

    dim3 ggrid(DD / 128, BS / 128);   // 32 x 32
    dim3 gblk(256);

    gemm_tc_kernel<true ><<<ggrid, gblk, GEMM_SMEM_BYTES>>>(x, wq, pq, cosb, sinb);
    gemm_tc_kernel<true ><<<ggrid, gblk, GEMM_SMEM_BYTES>>>(x, wk, pk, cosb, sinb);
    gemm_tc_kernel<false><<<ggrid, gblk, GEMM_SMEM_BYTES>>>(x, wv, pv, nullptr, nullptr);

    dim3 agrid(SS / 64, BB * HH);     // 16 x 128
    attn_kernel<<<agrid, dim3(256), attn_smem>>>(pq, pk, pv, pa);

    gemm_tc_kernel<false><<<ggrid, gblk, GEMM_SMEM_BYTES>>>(pa, wo, out, nullptr, nullptr);
}